// round 2
// baseline (speedup 1.0000x reference)
#include <cuda_runtime.h>
#include <math.h>

#define HS 1024
#define SS 2048
#define VS 50257

// ---------------- scratch (device globals; no allocation allowed) -------------
__device__ float g_gi[3 * HS];     // gate input  (x @ W_ih^T + b_ih)
__device__ float g_gh[3 * HS];     // gate hidden (h @ W_hh^T + b_hh)
__device__ float g_h0[HS];
__device__ float g_h1[HS];
__device__ float g_energ[SS];
__device__ float g_w[SS];          // attention weights
__device__ float g_cat[2 * HS];    // [h1, context]
__device__ float g_red[1];         // logsumexp scalar

// ---------------- reductions --------------------------------------------------
__device__ __forceinline__ float blockReduceSum(float v) {
    __shared__ float sm[32];
    int lane = threadIdx.x & 31, wid = threadIdx.x >> 5;
    #pragma unroll
    for (int o = 16; o > 0; o >>= 1) v += __shfl_down_sync(0xffffffffu, v, o);
    if (lane == 0) sm[wid] = v;
    __syncthreads();
    int nw = (blockDim.x + 31) >> 5;
    float r = (threadIdx.x < nw) ? sm[threadIdx.x] : 0.0f;
    __syncthreads();
    if (wid == 0) {
        #pragma unroll
        for (int o = 16; o > 0; o >>= 1) r += __shfl_down_sync(0xffffffffu, r, o);
    }
    return r;  // valid on thread 0
}

__device__ __forceinline__ float blockReduceMax(float v) {
    __shared__ float sm[32];
    int lane = threadIdx.x & 31, wid = threadIdx.x >> 5;
    #pragma unroll
    for (int o = 16; o > 0; o >>= 1) v = fmaxf(v, __shfl_down_sync(0xffffffffu, v, o));
    if (lane == 0) sm[wid] = v;
    __syncthreads();
    int nw = (blockDim.x + 31) >> 5;
    float r = (threadIdx.x < nw) ? sm[threadIdx.x] : -INFINITY;
    __syncthreads();
    if (wid == 0) {
        #pragma unroll
        for (int o = 16; o > 0; o >>= 1) r = fmaxf(r, __shfl_down_sync(0xffffffffu, r, o));
    }
    return r;  // valid on thread 0
}

// inner dot: W row (float4) against x (float4), n4 float4 elements
__device__ __forceinline__ float dot4(const float4* __restrict__ Wr,
                                      const float4* __restrict__ xv, int n4) {
    float acc = 0.0f;
    #pragma unroll 4
    for (int i = threadIdx.x; i < n4; i += blockDim.x) {
        float4 w4 = Wr[i];
        float4 x4 = xv[i];
        acc = fmaf(w4.x, x4.x, fmaf(w4.y, x4.y, fmaf(w4.z, x4.z, fmaf(w4.w, x4.w, acc))));
    }
    return acc;
}

// ---------------- kernels -----------------------------------------------------

// Layer-0 matvecs, fused. grid = 6*HS blocks x 128 thr.
// blocks [0, 3H): g_gi[row] = W_ih0[row,:] . [emb[word], last_context] + b_ih0[row]
// blocks [3H,6H): g_gh[row] = W_hh0[row,:] . last_hidden[0] + b_hh0[row]
__global__ void k_layer0(const int* __restrict__ word,
                         const float* __restrict__ emb,
                         const float* __restrict__ last_context,
                         const float* __restrict__ last_hidden,
                         const float* __restrict__ W_ih0,
                         const float* __restrict__ b_ih0,
                         const float* __restrict__ W_hh0,
                         const float* __restrict__ b_hh0) {
    int blk = blockIdx.x;
    if (blk < 3 * HS) {
        int row = blk;
        const float4* Wr = reinterpret_cast<const float4*>(W_ih0 + (size_t)row * (2 * HS));
        long w = (long)word[0];
        const float4* e4 = reinterpret_cast<const float4*>(emb + w * HS);
        const float4* c4 = reinterpret_cast<const float4*>(last_context);
        float acc = 0.0f;
        // first half: emb row, second half: last_context
        #pragma unroll 4
        for (int i = threadIdx.x; i < HS / 4; i += blockDim.x) {
            float4 w4 = Wr[i];
            float4 x4 = e4[i];
            acc = fmaf(w4.x, x4.x, fmaf(w4.y, x4.y, fmaf(w4.z, x4.z, fmaf(w4.w, x4.w, acc))));
        }
        #pragma unroll 4
        for (int i = threadIdx.x; i < HS / 4; i += blockDim.x) {
            float4 w4 = Wr[HS / 4 + i];
            float4 x4 = c4[i];
            acc = fmaf(w4.x, x4.x, fmaf(w4.y, x4.y, fmaf(w4.z, x4.z, fmaf(w4.w, x4.w, acc))));
        }
        float s = blockReduceSum(acc);
        if (threadIdx.x == 0) g_gi[row] = s + __ldg(&b_ih0[row]);
    } else {
        int row = blk - 3 * HS;
        const float4* Wr = reinterpret_cast<const float4*>(W_hh0 + (size_t)row * HS);
        const float4* h4 = reinterpret_cast<const float4*>(last_hidden);  // layer 0
        float s = blockReduceSum(dot4(Wr, h4, HS / 4));
        if (threadIdx.x == 0) g_gh[row] = s + __ldg(&b_hh0[row]);
    }
}

// GRU gate fusion layer 0: writes g_h0 and out_hid0.  1 block x 1024.
__global__ void k_gru0(const float* __restrict__ last_hidden, float* __restrict__ out_hid0) {
    int t = threadIdx.x;
    float r = 1.0f / (1.0f + expf(-(g_gi[t] + g_gh[t])));
    float z = 1.0f / (1.0f + expf(-(g_gi[HS + t] + g_gh[HS + t])));
    float n = tanhf(g_gi[2 * HS + t] + r * g_gh[2 * HS + t]);
    float h = (1.0f - z) * n + z * last_hidden[t];
    g_h0[t] = h;
    out_hid0[t] = h;
}

// Layer-1 matvecs, fused. grid = 6*HS blocks x 128 thr.
__global__ void k_layer1(const float* __restrict__ last_hidden,
                         const float* __restrict__ W_ih1,
                         const float* __restrict__ b_ih1,
                         const float* __restrict__ W_hh1,
                         const float* __restrict__ b_hh1) {
    int blk = blockIdx.x;
    if (blk < 3 * HS) {
        int row = blk;
        const float4* Wr = reinterpret_cast<const float4*>(W_ih1 + (size_t)row * HS);
        const float4* x4 = reinterpret_cast<const float4*>(g_h0);
        float s = blockReduceSum(dot4(Wr, x4, HS / 4));
        if (threadIdx.x == 0) g_gi[row] = s + __ldg(&b_ih1[row]);
    } else {
        int row = blk - 3 * HS;
        const float4* Wr = reinterpret_cast<const float4*>(W_hh1 + (size_t)row * HS);
        const float4* h4 = reinterpret_cast<const float4*>(last_hidden + HS);  // layer 1
        float s = blockReduceSum(dot4(Wr, h4, HS / 4));
        if (threadIdx.x == 0) g_gh[row] = s + __ldg(&b_hh1[row]);
    }
}

// GRU gate fusion layer 1: writes g_h1 and out_hid1.  1 block x 1024.
__global__ void k_gru1(const float* __restrict__ last_hidden, float* __restrict__ out_hid1) {
    int t = threadIdx.x;
    float r = 1.0f / (1.0f + expf(-(g_gi[t] + g_gh[t])));
    float z = 1.0f / (1.0f + expf(-(g_gi[HS + t] + g_gh[HS + t])));
    float n = tanhf(g_gi[2 * HS + t] + r * g_gh[2 * HS + t]);
    float h = (1.0f - z) * n + z * last_hidden[HS + t];
    g_h1[t] = h;
    out_hid1[t] = h;
}

// attention energies: grid SS x 128. g_energ[s] = enc[s,:] . g_h1
__global__ void k_energ(const float* __restrict__ enc) {
    int row = blockIdx.x;
    const float4* Er = reinterpret_cast<const float4*>(enc + (size_t)row * HS);
    const float4* h4 = reinterpret_cast<const float4*>(g_h1);
    float s = blockReduceSum(dot4(Er, h4, HS / 4));
    if (threadIdx.x == 0) g_energ[row] = s;
}

// softmax over g_energ[S] -> g_w + out_attn.   1 block x 1024.
__global__ void k_softmax(float* __restrict__ out_attn) {
    __shared__ float sbc;
    int t = threadIdx.x;
    float e0 = g_energ[t], e1 = g_energ[t + HS];
    float m = blockReduceMax(fmaxf(e0, e1));
    if (t == 0) sbc = m;
    __syncthreads();
    float mx = sbc;
    float x0 = expf(e0 - mx), x1 = expf(e1 - mx);
    float s = blockReduceSum(x0 + x1);
    if (t == 0) sbc = s;
    __syncthreads();
    float inv = 1.0f / sbc;
    x0 *= inv; x1 *= inv;
    g_w[t] = x0;        g_w[t + HS] = x1;
    out_attn[t] = x0;   out_attn[t + HS] = x1;
}

// context[h] = sum_s w[s]*enc[s][h]; build g_cat = [h1, ctx].  grid 8 x 128.
__global__ void k_context(const float* __restrict__ enc, float* __restrict__ out_ctx) {
    int t = blockIdx.x * blockDim.x + threadIdx.x;  // 0..1023
    float acc = 0.0f;
    #pragma unroll 4
    for (int s = 0; s < SS; s++)
        acc = fmaf(g_w[s], enc[(size_t)s * HS + t], acc);
    out_ctx[t] = acc;
    g_cat[t] = g_h1[t];
    g_cat[HS + t] = acc;
}

// output projection: grid VS x 128. out_logits[row] = W_out[row,:] . g_cat + b_out
__global__ void k_out(const float* __restrict__ W_out, const float* __restrict__ b_out,
                      float* __restrict__ out_logits) {
    int row = blockIdx.x;
    const float4* Wr = reinterpret_cast<const float4*>(W_out + (size_t)row * (2 * HS));
    const float4* x4 = reinterpret_cast<const float4*>(g_cat);
    float s = blockReduceSum(dot4(Wr, x4, 2 * HS / 4));
    if (threadIdx.x == 0) out_logits[row] = s + __ldg(&b_out[row]);
}

// logsumexp over logits[V].  1 block x 1024.
__global__ void k_lse(const float* __restrict__ logits) {
    int t = threadIdx.x;
    float m = -INFINITY;
    for (int i = t; i < VS; i += 1024) m = fmaxf(m, logits[i]);
    m = blockReduceMax(m);
    __shared__ float sbc;
    if (t == 0) sbc = m;
    __syncthreads();
    float mx = sbc;
    float s = 0.0f;
    for (int i = t; i < VS; i += 1024) s += expf(logits[i] - mx);
    s = blockReduceSum(s);
    if (t == 0) g_red[0] = mx + logf(s);
}

// out[i] = logit[i] - logsumexp
__global__ void k_final(float* __restrict__ out) {
    int i = blockIdx.x * blockDim.x + threadIdx.x;
    if (i < VS) out[i] -= g_red[0];
}

// ---------------- launch ------------------------------------------------------
extern "C" void kernel_launch(void* const* d_in, const int* in_sizes, int n_in,
                              void* d_out, int out_size) {
    const int*   word         = (const int*)  d_in[0];
    const float* last_context = (const float*)d_in[1];
    const float* last_hidden  = (const float*)d_in[2];   // (2,1,H)
    const float* enc          = (const float*)d_in[3];   // (S,1,H) == (S,H)
    const float* emb          = (const float*)d_in[4];
    const float* W_ih0        = (const float*)d_in[5];
    const float* W_hh0        = (const float*)d_in[6];
    const float* b_ih0        = (const float*)d_in[7];
    const float* b_hh0        = (const float*)d_in[8];
    const float* W_ih1        = (const float*)d_in[9];
    const float* W_hh1        = (const float*)d_in[10];
    const float* b_ih1        = (const float*)d_in[11];
    const float* b_hh1        = (const float*)d_in[12];
    const float* W_out        = (const float*)d_in[13];
    const float* b_out        = (const float*)d_in[14];

    float* out = (float*)d_out;
    float* out_logits = out;                   // V
    float* out_ctx    = out + VS;              // H
    float* out_hid0   = out + VS + HS;         // H
    float* out_hid1   = out + VS + 2 * HS;     // H
    float* out_attn   = out + VS + 3 * HS;     // S

    k_layer0 <<<6 * HS, 128>>>(word, emb, last_context, last_hidden,
                               W_ih0, b_ih0, W_hh0, b_hh0);
    k_gru0   <<<1, 1024>>>(last_hidden, out_hid0);
    k_layer1 <<<6 * HS, 128>>>(last_hidden, W_ih1, b_ih1, W_hh1, b_hh1);
    k_gru1   <<<1, 1024>>>(last_hidden, out_hid1);
    k_energ  <<<SS, 128>>>(enc);
    k_softmax<<<1, 1024>>>(out_attn);
    k_context<<<8, 128>>>(enc, out_ctx);
    k_out    <<<VS, 128>>>(W_out, b_out, out_logits);
    k_lse    <<<1, 1024>>>(out_logits);
    k_final  <<<(VS + 255) / 256, 256>>>(out_logits);
}

// round 3
// speedup vs baseline: 1.9602x; 1.9602x over previous
#include <cuda_runtime.h>
#include <math.h>

#define HS 1024
#define SS 2048
#define VS 50257
#define NB 148
#define NT 512
#define NWARPS ((NB * NT) / 32)   // 2368

// ---------------- scratch (device globals; no allocation allowed) -------------
__device__ float g_x0[2 * HS];      // rnn_input = [emb_row, last_context]
__device__ float g_gi[3 * HS];
__device__ float g_gh[3 * HS];
__device__ float g_h0[HS];
__device__ float g_h1[HS];
__device__ float g_energ[SS];
__device__ float g_w[SS];
__device__ float g_cat[2 * HS];     // [h1, context]
__device__ float g_part[NB][HS];    // per-block context partials (deterministic)
__device__ float g_pm[NB];          // per-block logit max
__device__ float g_ps[NB];          // per-block sum exp(x - m_b)
__device__ float g_red;             // logsumexp
__device__ volatile unsigned g_bar_gen;  // statically 0
__device__ unsigned g_bar_cnt;           // statically 0

// ---------------- grid barrier (all 148 blocks co-resident) -------------------
__device__ __forceinline__ void grid_barrier() {
    __syncthreads();
    if (threadIdx.x == 0) {
        __threadfence();
        unsigned gen = g_bar_gen;
        if (atomicAdd(&g_bar_cnt, 1u) == NB - 1) {
            g_bar_cnt = 0;
            __threadfence();
            g_bar_gen = gen + 1;
        } else {
            while (g_bar_gen == gen) __nanosleep(32);
            __threadfence();
        }
    }
    __syncthreads();
}

// ---------------- reductions --------------------------------------------------
__device__ __forceinline__ float warpSum(float v) {
    #pragma unroll
    for (int o = 16; o > 0; o >>= 1) v += __shfl_down_sync(0xffffffffu, v, o);
    return v;
}
__device__ __forceinline__ float warpMax(float v) {
    #pragma unroll
    for (int o = 16; o > 0; o >>= 1) v = fmaxf(v, __shfl_down_sync(0xffffffffu, v, o));
    return v;
}
__device__ __forceinline__ float blockSum(float v) {  // valid on thread 0
    __shared__ float sm[32];
    int lane = threadIdx.x & 31, wid = threadIdx.x >> 5;
    v = warpSum(v);
    if (lane == 0) sm[wid] = v;
    __syncthreads();
    float r = (threadIdx.x < NT / 32) ? sm[threadIdx.x] : 0.0f;
    __syncthreads();
    if (wid == 0) r = warpSum(r);
    return r;
}
__device__ __forceinline__ float blockMax(float v) {  // valid on thread 0
    __shared__ float sm[32];
    int lane = threadIdx.x & 31, wid = threadIdx.x >> 5;
    v = warpMax(v);
    if (lane == 0) sm[wid] = v;
    __syncthreads();
    float r = (threadIdx.x < NT / 32) ? sm[threadIdx.x] : -INFINITY;
    __syncthreads();
    if (wid == 0) r = warpMax(r);
    return r;
}

__device__ __forceinline__ float fma4(float4 w, float4 x, float a) {
    return fmaf(w.x, x.x, fmaf(w.y, x.y, fmaf(w.z, x.z, fmaf(w.w, x.w, a))));
}

__device__ __forceinline__ float sigmoidf_(float x) { return 1.0f / (1.0f + expf(-x)); }

// ---------------- the single fused kernel -------------------------------------
__global__ void __launch_bounds__(NT, 1)
fused_seq2seq(const int* __restrict__ word,
              const float* __restrict__ ctx_in,
              const float* __restrict__ hid_in,     // (2, H)
              const float* __restrict__ enc,        // (S, H)
              const float* __restrict__ emb,
              const float* __restrict__ Wih0, const float* __restrict__ Whh0,
              const float* __restrict__ bih0, const float* __restrict__ bhh0,
              const float* __restrict__ Wih1, const float* __restrict__ Whh1,
              const float* __restrict__ bih1, const float* __restrict__ bhh1,
              const float* __restrict__ Wout, const float* __restrict__ bout,
              float* __restrict__ out_logits, float* __restrict__ out_ctx,
              float* __restrict__ out_hid0, float* __restrict__ out_hid1,
              float* __restrict__ out_attn) {
    const int tid  = threadIdx.x;
    const int gtid = blockIdx.x * NT + tid;
    const int lane = tid & 31;
    const int gw   = gtid >> 5;
    __shared__ float s_bc;

    // ── ph0: build rnn_input = [emb[word], last_context] ──
    if (gtid < 2 * HS)
        g_x0[gtid] = (gtid < HS) ? emb[(size_t)word[0] * HS + gtid]
                                 : ctx_in[gtid - HS];
    grid_barrier();  // B0

    // ── ph1: layer-0 matvecs (warp per row) ──
    {
        const float4* x4 = (const float4*)g_x0;     // 512 float4
        const float4* h4 = (const float4*)hid_in;   // layer-0 hidden, 256 float4
        for (int t = gw; t < 6 * HS; t += NWARPS) {
            if (t < 3 * HS) {
                int row = t;
                const float4* Wr = (const float4*)(Wih0 + (size_t)row * (2 * HS));
                float a = 0.0f;
                #pragma unroll
                for (int i = 0; i < 16; i++) {
                    int idx = lane + 32 * i;
                    a = fma4(__ldg(Wr + idx), x4[idx], a);
                }
                a = warpSum(a);
                if (lane == 0) g_gi[row] = a + __ldg(bih0 + row);
            } else {
                int row = t - 3 * HS;
                const float4* Wr = (const float4*)(Whh0 + (size_t)row * HS);
                float a = 0.0f;
                #pragma unroll
                for (int i = 0; i < 8; i++) {
                    int idx = lane + 32 * i;
                    a = fma4(__ldg(Wr + idx), h4[idx], a);
                }
                a = warpSum(a);
                if (lane == 0) g_gh[row] = a + __ldg(bhh0 + row);
            }
        }
    }
    grid_barrier();  // B1

    // ── ph2: GRU gates layer 0 (block 0) ──
    if (blockIdx.x == 0) {
        for (int e = tid; e < HS; e += NT) {
            float r = sigmoidf_(g_gi[e] + g_gh[e]);
            float z = sigmoidf_(g_gi[HS + e] + g_gh[HS + e]);
            float n = tanhf(g_gi[2 * HS + e] + r * g_gh[2 * HS + e]);
            float h = (1.0f - z) * n + z * hid_in[e];
            g_h0[e] = h;
            out_hid0[e] = h;
        }
    }
    grid_barrier();  // B2

    // ── ph3: layer-1 matvecs ──
    {
        const float4* x4 = (const float4*)g_h0;
        const float4* h4 = (const float4*)(hid_in + HS);
        for (int t = gw; t < 6 * HS; t += NWARPS) {
            int row; const float4* Wr; const float4* xv; const float* bia; float* dst;
            if (t < 3 * HS) { row = t;          Wr = (const float4*)(Wih1 + (size_t)row * HS); xv = x4; bia = bih1; dst = g_gi; }
            else            { row = t - 3 * HS; Wr = (const float4*)(Whh1 + (size_t)row * HS); xv = h4; bia = bhh1; dst = g_gh; }
            float a = 0.0f;
            #pragma unroll
            for (int i = 0; i < 8; i++) {
                int idx = lane + 32 * i;
                a = fma4(__ldg(Wr + idx), xv[idx], a);
            }
            a = warpSum(a);
            if (lane == 0) dst[row] = a + __ldg(bia + row);
        }
    }
    grid_barrier();  // B3

    // ── ph4: GRU gates layer 1 (block 0) ──
    if (blockIdx.x == 0) {
        for (int e = tid; e < HS; e += NT) {
            float r = sigmoidf_(g_gi[e] + g_gh[e]);
            float z = sigmoidf_(g_gi[HS + e] + g_gh[HS + e]);
            float n = tanhf(g_gi[2 * HS + e] + r * g_gh[2 * HS + e]);
            float h = (1.0f - z) * n + z * hid_in[HS + e];
            g_h1[e] = h;
            out_hid1[e] = h;
        }
    }
    grid_barrier();  // B4

    // ── ph5: attention energies (warp per row) ──
    {
        const float4* h4 = (const float4*)g_h1;
        for (int t = gw; t < SS; t += NWARPS) {
            const float4* Er = (const float4*)(enc + (size_t)t * HS);
            float a = 0.0f;
            #pragma unroll
            for (int i = 0; i < 8; i++) {
                int idx = lane + 32 * i;
                a = fma4(__ldg(Er + idx), h4[idx], a);
            }
            a = warpSum(a);
            if (lane == 0) g_energ[t] = a;
        }
    }
    grid_barrier();  // B5

    // ── ph6: softmax (block 0); block 1 copies h1 -> g_cat[0:H) ──
    if (blockIdx.x == 0) {
        float e0 = g_energ[tid],            e1 = g_energ[tid + 512];
        float e2 = g_energ[tid + 1024],     e3 = g_energ[tid + 1536];
        float m = blockMax(fmaxf(fmaxf(e0, e1), fmaxf(e2, e3)));
        if (tid == 0) s_bc = m;
        __syncthreads();
        float mx = s_bc;
        float x0 = expf(e0 - mx), x1 = expf(e1 - mx);
        float x2 = expf(e2 - mx), x3 = expf(e3 - mx);
        float s = blockSum(x0 + x1 + x2 + x3);
        if (tid == 0) s_bc = s;
        __syncthreads();
        float inv = 1.0f / s_bc;
        x0 *= inv; x1 *= inv; x2 *= inv; x3 *= inv;
        g_w[tid] = x0;        g_w[tid + 512] = x1;
        g_w[tid + 1024] = x2; g_w[tid + 1536] = x3;
        out_attn[tid] = x0;        out_attn[tid + 512] = x1;
        out_attn[tid + 1024] = x2; out_attn[tid + 1536] = x3;
    } else if (blockIdx.x == 1) {
        g_cat[tid]       = g_h1[tid];
        g_cat[tid + 512] = g_h1[tid + 512];
    }
    grid_barrier();  // B6

    // ── ph7: context partials — block b handles s-slice, all 1024 cols ──
    {
        const int SCH = (SS + NB - 1) / NB;   // 14
        int s0 = blockIdx.x * SCH;
        int s1 = min(s0 + SCH, SS);
        int c0 = tid * 2;                     // two columns per thread
        float a0 = 0.0f, a1 = 0.0f;
        for (int s = s0; s < s1; s++) {
            float wv = g_w[s];
            float2 ev = ((const float2*)(enc + (size_t)s * HS))[tid];
            a0 = fmaf(wv, ev.x, a0);
            a1 = fmaf(wv, ev.y, a1);
        }
        ((float2*)&g_part[blockIdx.x][c0])[0] = make_float2(a0, a1);
    }
    grid_barrier();  // B7

    // ── ph7b: reduce partials -> g_cat[H:2H), out_ctx ──
    if (gtid < HS) {
        float s = 0.0f;
        #pragma unroll 4
        for (int b = 0; b < NB; b++) s += g_part[b][gtid];
        g_cat[HS + gtid] = s;
        out_ctx[gtid] = s;
    }
    grid_barrier();  // B8

    // ── ph8: output projection (dominant, 412 MB) — warp per row, x in regs ──
    {
        const float4* cat4 = (const float4*)g_cat;   // 512 float4
        float4 xr[16];
        #pragma unroll
        for (int i = 0; i < 16; i++) xr[i] = __ldcg(cat4 + lane + 32 * i);
        for (int row = gw; row < VS; row += NWARPS) {
            const float4* Wr = (const float4*)(Wout + (size_t)row * (2 * HS));
            float a = 0.0f;
            #pragma unroll
            for (int i = 0; i < 16; i++)
                a = fma4(__ldg(Wr + lane + 32 * i), xr[i], a);
            a = warpSum(a);
            if (lane == 0) out_logits[row] = a + __ldg(bout + row);
        }
    }
    grid_barrier();  // B9

    // ── ph9a: per-block partial (max, sum-exp) over a contiguous logit chunk ──
    {
        const int CH = (VS + NB - 1) / NB;    // 340
        int i0 = blockIdx.x * CH;
        int idx = i0 + tid;
        bool valid = (tid < CH) && (idx < VS);
        float v = valid ? out_logits[idx] : -INFINITY;
        float m = blockMax(v);
        if (tid == 0) s_bc = m;
        __syncthreads();
        float mx = s_bc;
        float p = valid ? expf(v - mx) : 0.0f;
        float s = blockSum(p);
        if (tid == 0) { g_pm[blockIdx.x] = mx; g_ps[blockIdx.x] = s; }
    }
    grid_barrier();  // B10

    // ── ph9b: combine 148 partials (block 0) ──
    if (blockIdx.x == 0) {
        float m = (tid < NB) ? g_pm[tid] : -INFINITY;
        float M = blockMax(m);
        if (tid == 0) s_bc = M;
        __syncthreads();
        float Mx = s_bc;
        float p = (tid < NB) ? g_ps[tid] * expf(g_pm[tid] - Mx) : 0.0f;
        float S = blockSum(p);
        if (tid == 0) g_red = Mx + logf(S);
    }
    grid_barrier();  // B11

    // ── ph9c: subtract logsumexp ──
    {
        float r = g_red;
        for (int i = gtid; i < VS; i += NB * NT) out_logits[i] -= r;
    }
}

// ---------------- launch ------------------------------------------------------
extern "C" void kernel_launch(void* const* d_in, const int* in_sizes, int n_in,
                              void* d_out, int out_size) {
    const int*   word         = (const int*)  d_in[0];
    const float* last_context = (const float*)d_in[1];
    const float* last_hidden  = (const float*)d_in[2];
    const float* enc          = (const float*)d_in[3];
    const float* emb          = (const float*)d_in[4];
    const float* W_ih0        = (const float*)d_in[5];
    const float* W_hh0        = (const float*)d_in[6];
    const float* b_ih0        = (const float*)d_in[7];
    const float* b_hh0        = (const float*)d_in[8];
    const float* W_ih1        = (const float*)d_in[9];
    const float* W_hh1        = (const float*)d_in[10];
    const float* b_ih1        = (const float*)d_in[11];
    const float* b_hh1        = (const float*)d_in[12];
    const float* W_out        = (const float*)d_in[13];
    const float* b_out        = (const float*)d_in[14];

    float* out = (float*)d_out;
    float* out_logits = out;                 // V
    float* out_ctx    = out + VS;            // H
    float* out_hid0   = out + VS + HS;       // H
    float* out_hid1   = out + VS + 2 * HS;   // H
    float* out_attn   = out + VS + 3 * HS;   // S

    fused_seq2seq<<<NB, NT>>>(word, last_context, last_hidden, enc, emb,
                              W_ih0, W_hh0, b_ih0, b_hh0,
                              W_ih1, W_hh1, b_ih1, b_hh1,
                              W_out, b_out,
                              out_logits, out_ctx, out_hid0, out_hid1, out_attn);
}

// round 7
// speedup vs baseline: 2.1945x; 1.1195x over previous
#include <cuda_runtime.h>
#include <math.h>

#define HS 1024
#define SS 2048
#define VS 50257
#define NB 148
#define NT 1024
#define NWB 32                      // warps per block
#define NWARPS (NB * NWB)           // 4736
#define CHS ((SS + NB - 1) / NB)    // 14 s-rows per block (context)
#define CHV ((VS + NB - 1) / NB)    // 340 logit rows per block
#define CHH ((HS + NB - 1) / NB)    // 7 ctx columns per block (partial reduce)

// ---------------- scratch (device globals; no allocation allowed) -------------
__device__ float g_gi[3 * HS];          // layer-0 gate-input
__device__ float g_gh[3 * HS];          // layer-0 gate-hidden
__device__ float g_gi2[3 * HS];         // layer-1 (separate buffers: no extra barrier)
__device__ float g_gh2[3 * HS];
__device__ float g_h1[HS];
__device__ float g_energ[SS];
__device__ float g_ctx[HS];
__device__ float g_part[NB][HS];        // per-block context partials (deterministic)
__device__ float g_pm[NB];              // per-block logit max
__device__ float g_ps[NB];              // per-block sum exp
__device__ volatile unsigned g_bar_gen; // statically 0
__device__ unsigned g_bar_cnt;          // statically 0

// ---------------- grid barrier (all 148 blocks co-resident) -------------------
__device__ __forceinline__ void grid_barrier() {
    __syncthreads();
    if (threadIdx.x == 0) {
        __threadfence();
        unsigned gen = g_bar_gen;
        if (atomicAdd(&g_bar_cnt, 1u) == NB - 1) {
            g_bar_cnt = 0;
            __threadfence();
            g_bar_gen = gen + 1;
        } else {
            while (g_bar_gen == gen) __nanosleep(32);
            __threadfence();
        }
    }
    __syncthreads();
}

// ---------------- reductions --------------------------------------------------
__device__ __forceinline__ float warpSum(float v) {
    #pragma unroll
    for (int o = 16; o > 0; o >>= 1) v += __shfl_down_sync(0xffffffffu, v, o);
    return v;
}
__device__ __forceinline__ float warpMax(float v) {
    #pragma unroll
    for (int o = 16; o > 0; o >>= 1) v = fmaxf(v, __shfl_down_sync(0xffffffffu, v, o));
    return v;
}
__device__ __forceinline__ float blockSum(float v, float* sm) {  // valid on thread 0
    int lane = threadIdx.x & 31, wid = threadIdx.x >> 5;
    v = warpSum(v);
    if (lane == 0) sm[wid] = v;
    __syncthreads();
    float r = (threadIdx.x < NWB) ? sm[threadIdx.x] : 0.0f;
    __syncthreads();
    if (wid == 0) r = warpSum(r);
    return r;
}
__device__ __forceinline__ float blockMax(float v, float* sm) {  // valid on thread 0
    int lane = threadIdx.x & 31, wid = threadIdx.x >> 5;
    v = warpMax(v);
    if (lane == 0) sm[wid] = v;
    __syncthreads();
    float r = (threadIdx.x < NWB) ? sm[threadIdx.x] : -INFINITY;
    __syncthreads();
    if (wid == 0) r = warpMax(r);
    return r;
}

__device__ __forceinline__ float fma4(float4 w, float4 x, float a) {
    return fmaf(w.x, x.x, fmaf(w.y, x.y, fmaf(w.z, x.z, fmaf(w.w, x.w, a))));
}
__device__ __forceinline__ float sigmoidf_(float x) { return 1.0f / (1.0f + expf(-x)); }

// 2048-col dot: W row (global) . x (smem float4[512])
__device__ __forceinline__ float dot2048(const float4* __restrict__ Wr,
                                         const float4* __restrict__ sx, int lane) {
    float a0 = 0.f, a1 = 0.f, a2 = 0.f, a3 = 0.f;
    #pragma unroll
    for (int i = 0; i < 4; i++) {
        int idx = lane + 128 * i;
        float4 w0 = __ldg(Wr + idx),       x0 = sx[idx];
        float4 w1 = __ldg(Wr + idx + 32),  x1 = sx[idx + 32];
        float4 w2 = __ldg(Wr + idx + 64),  x2 = sx[idx + 64];
        float4 w3 = __ldg(Wr + idx + 96),  x3 = sx[idx + 96];
        a0 = fma4(w0, x0, a0); a1 = fma4(w1, x1, a1);
        a2 = fma4(w2, x2, a2); a3 = fma4(w3, x3, a3);
    }
    return warpSum((a0 + a1) + (a2 + a3));
}

// 1024-col dot: W row (global) . x (smem float4[256])
__device__ __forceinline__ float dot1024(const float4* __restrict__ Wr,
                                         const float4* __restrict__ sx, int lane) {
    float a0 = 0.f, a1 = 0.f, a2 = 0.f, a3 = 0.f;
    #pragma unroll
    for (int i = 0; i < 2; i++) {
        int idx = lane + 128 * i;
        float4 w0 = __ldg(Wr + idx),       x0 = sx[idx];
        float4 w1 = __ldg(Wr + idx + 32),  x1 = sx[idx + 32];
        float4 w2 = __ldg(Wr + idx + 64),  x2 = sx[idx + 64];
        float4 w3 = __ldg(Wr + idx + 96),  x3 = sx[idx + 96];
        a0 = fma4(w0, x0, a0); a1 = fma4(w1, x1, a1);
        a2 = fma4(w2, x2, a2); a3 = fma4(w3, x3, a3);
    }
    return warpSum((a0 + a1) + (a2 + a3));
}

// ---------------- the single fused kernel -------------------------------------
__global__ void __launch_bounds__(NT, 1)
fused_seq2seq(const int* __restrict__ word,
              const float* __restrict__ ctx_in,
              const float* __restrict__ hid_in,     // (2, H)
              const float* __restrict__ enc,        // (S, H)
              const float* __restrict__ emb,
              const float* __restrict__ Wih0, const float* __restrict__ Whh0,
              const float* __restrict__ bih0, const float* __restrict__ bhh0,
              const float* __restrict__ Wih1, const float* __restrict__ Whh1,
              const float* __restrict__ bih1, const float* __restrict__ bhh1,
              const float* __restrict__ Wout, const float* __restrict__ bout,
              float* __restrict__ out_logits, float* __restrict__ out_ctx,
              float* __restrict__ out_hid0, float* __restrict__ out_hid1,
              float* __restrict__ out_attn) {
    __shared__ float4 s_x4[512];            // 8 KB main x buffer (2048 floats)
    __shared__ float4 s_h4[256];            // 4 KB secondary x buffer (1024 floats)
    __shared__ float  s_red[32];
    __shared__ float  s_bc;
    __shared__ float  s_w[CHS];

    float* s_x = (float*)s_x4;
    float* s_h = (float*)s_h4;

    const int tid  = threadIdx.x;
    const int lane = tid & 31;
    const int wid  = tid >> 5;
    const int gw   = blockIdx.x * NWB + wid;   // global warp id

    // ── ph1: layer-0 matvecs.  x0=[emb,ctx] in s_x, hid0 in s_h ──
    s_x[tid]      = emb[(size_t)word[0] * HS + tid];
    s_x[HS + tid] = ctx_in[tid];
    s_h[tid]      = hid_in[tid];
    __syncthreads();
    for (int t = gw; t < 6 * HS; t += NWARPS) {
        if (t < 3 * HS) {
            float a = dot2048((const float4*)(Wih0 + (size_t)t * (2 * HS)), s_x4, lane);
            if (lane == 0) g_gi[t] = a + __ldg(bih0 + t);
        } else {
            int row = t - 3 * HS;
            float a = dot1024((const float4*)(Whh0 + (size_t)row * HS), s_h4, lane);
            if (lane == 0) g_gh[row] = a + __ldg(bhh0 + row);
        }
    }
    grid_barrier();  // B1

    // ── ph2': redundant layer-0 gates -> s_x[0:H); hid1 -> s_h ──
    {
        float r = sigmoidf_(g_gi[tid] + g_gh[tid]);
        float z = sigmoidf_(g_gi[HS + tid] + g_gh[HS + tid]);
        float n = tanhf(g_gi[2 * HS + tid] + r * g_gh[2 * HS + tid]);
        float h = (1.0f - z) * n + z * hid_in[tid];
        if (blockIdx.x == 0) out_hid0[tid] = h;
        float h1prev = hid_in[HS + tid];
        __syncthreads();            // s_x/s_h no longer read as ph1 operands
        s_x[tid] = h;
        s_h[tid] = h1prev;
    }
    __syncthreads();

    // ── ph3: layer-1 matvecs ──
    for (int t = gw; t < 6 * HS; t += NWARPS) {
        if (t < 3 * HS) {
            float a = dot1024((const float4*)(Wih1 + (size_t)t * HS), s_x4, lane);
            if (lane == 0) g_gi2[t] = a + __ldg(bih1 + t);
        } else {
            int row = t - 3 * HS;
            float a = dot1024((const float4*)(Whh1 + (size_t)row * HS), s_h4, lane);
            if (lane == 0) g_gh2[row] = a + __ldg(bhh1 + row);
        }
    }
    grid_barrier();  // B3

    // ── ph4': redundant layer-1 gates -> s_x[0:H) ──
    {
        float r = sigmoidf_(g_gi2[tid] + g_gh2[tid]);
        float z = sigmoidf_(g_gi2[HS + tid] + g_gh2[HS + tid]);
        float n = tanhf(g_gi2[2 * HS + tid] + r * g_gh2[2 * HS + tid]);
        float h = (1.0f - z) * n + z * hid_in[HS + tid];
        if (blockIdx.x == 0) { out_hid1[tid] = h; g_h1[tid] = h; }
        __syncthreads();
        s_x[tid] = h;
    }
    __syncthreads();

    // ── ph5: attention energies (warp per row) ──
    for (int t = gw; t < SS; t += NWARPS) {
        float a = dot1024((const float4*)(enc + (size_t)t * HS), s_x4, lane);
        if (lane == 0) g_energ[t] = a;
    }
    grid_barrier();  // B5

    // ── ph6': redundant softmax normalizer; weights for this block's s-slice ──
    {
        float e0 = g_energ[tid], e1 = g_energ[tid + HS];
        float m = blockMax(fmaxf(e0, e1), s_red);
        if (tid == 0) s_bc = m;
        __syncthreads();
        float mx = s_bc;
        float s = blockSum(expf(e0 - mx) + expf(e1 - mx), s_red);
        if (tid == 0) s_bc = s;
        __syncthreads();
        float inv = 1.0f / s_bc;
        int s0 = blockIdx.x * CHS;
        if (tid < CHS && s0 + tid < SS) {
            float wv = expf(g_energ[s0 + tid] - mx) * inv;
            s_w[tid] = wv;
            out_attn[s0 + tid] = wv;
        }
    }
    __syncthreads();

    // ── ph7: context partial over this block's s-slice (col per thread) ──
    {
        int s0 = blockIdx.x * CHS;
        int n  = min(CHS, SS - s0);
        float a = 0.0f;
        for (int j = 0; j < n; j++)
            a = fmaf(s_w[j], enc[(size_t)(s0 + j) * HS + tid], a);
        g_part[blockIdx.x][tid] = (n > 0) ? a : 0.0f;
    }
    grid_barrier();  // B7

    // ── ph7b: reduce partials — DISTRIBUTED: block b owns columns [b*CHH, ...) ──
    {
        int c = blockIdx.x * CHH + tid;     // tid < CHH only
        if (tid < CHH && c < HS) {
            float s = 0.0f;
            #pragma unroll 4
            for (int b = 0; b < NB; b++) s += g_part[b][c];
            g_ctx[c] = s;
            out_ctx[c] = s;
        }
    }
    grid_barrier();  // B8

    // ── ph8: output projection — block-contiguous rows, x=[h1,ctx] in smem ──
    {
        s_x[tid]      = g_h1[tid];
        s_x[HS + tid] = g_ctx[tid];
        __syncthreads();
        int base  = blockIdx.x * CHV;
        int nrows = min(CHV, VS - base);
        for (int r = wid; r < nrows; r += NWB) {
            int row = base + r;
            float a = dot2048((const float4*)(Wout + (size_t)row * (2 * HS)), s_x4, lane);
            if (lane == 0) out_logits[row] = a + __ldg(bout + row);
        }
        __syncthreads();

        // ph9a: block-local max/sum-exp over OWN rows (no grid barrier needed)
        int idx = base + tid;
        bool valid = (tid < nrows);
        float v = valid ? out_logits[idx] : -INFINITY;
        float m = blockMax(v, s_red);
        if (tid == 0) s_bc = m;
        __syncthreads();
        float mx = s_bc;
        float s = blockSum(valid ? expf(v - mx) : 0.0f, s_red);
        if (tid == 0) { g_pm[blockIdx.x] = mx; g_ps[blockIdx.x] = s; }
    }
    grid_barrier();  // B9

    // ── ph9b: redundant combine of 148 partials; subtract from own rows ──
    {
        float m = (tid < NB) ? g_pm[tid] : -INFINITY;
        float M = blockMax(m, s_red);
        if (tid == 0) s_bc = M;
        __syncthreads();
        float Mx = s_bc;
        float p = (tid < NB) ? g_ps[tid] * expf(g_pm[tid] - Mx) : 0.0f;
        float S = blockSum(p, s_red);
        if (tid == 0) s_bc = Mx + logf(S);
        __syncthreads();
        float lse = s_bc;
        int base  = blockIdx.x * CHV;
        int nrows = min(CHV, VS - base);
        if (tid < nrows) out_logits[base + tid] -= lse;
    }
}

// ---------------- launch ------------------------------------------------------
extern "C" void kernel_launch(void* const* d_in, const int* in_sizes, int n_in,
                              void* d_out, int out_size) {
    const int*   word         = (const int*)  d_in[0];
    const float* last_context = (const float*)d_in[1];
    const float* last_hidden  = (const float*)d_in[2];
    const float* enc          = (const float*)d_in[3];
    const float* emb          = (const float*)d_in[4];
    const float* W_ih0        = (const float*)d_in[5];
    const float* W_hh0        = (const float*)d_in[6];
    const float* b_ih0        = (const float*)d_in[7];
    const float* b_hh0        = (const float*)d_in[8];
    const float* W_ih1        = (const float*)d_in[9];
    const float* W_hh1        = (const float*)d_in[10];
    const float* b_ih1        = (const float*)d_in[11];
    const float* b_hh1        = (const float*)d_in[12];
    const float* W_out        = (const float*)d_in[13];
    const float* b_out        = (const float*)d_in[14];

    float* out = (float*)d_out;
    float* out_logits = out;                 // V
    float* out_ctx    = out + VS;            // H
    float* out_hid0   = out + VS + HS;       // H
    float* out_hid1   = out + VS + 2 * HS;   // H
    float* out_attn   = out + VS + 3 * HS;   // S

    fused_seq2seq<<<NB, NT>>>(word, last_context, last_hidden, enc, emb,
                              W_ih0, W_hh0, b_ih0, b_hh0,
                              W_ih1, W_hh1, b_ih1, b_hh1,
                              W_out, b_out,
                              out_logits, out_ctx, out_hid0, out_hid1, out_attn);
}

// round 8
// speedup vs baseline: 2.5364x; 1.1558x over previous
#include <cuda_runtime.h>
#include <math.h>

#define HS 1024
#define SS 2048
#define VS 50257
#define NB 148
#define NT 1024
#define NWB 32                      // warps per block
#define NWARPS (NB * NWB)           // 4736
#define CW 28                       // compute (streaming) warps per block
#define ATW 4                       // attention warps per block (tid 896..1023)
#define AWN (NB * ATW)              // 592 attention warps chip-wide
#define CHS ((SS + NB - 1) / NB)    // 14 s-rows per block (context slice)
#define CHV ((VS + NB - 1) / NB)    // 340 logit rows per block
#define CHH ((HS + NB - 1) / NB)    // 7 ctx columns per block (partial reduce)

// ---------------- scratch (device globals; no allocation allowed) -------------
__device__ float g_gi[3 * HS];
__device__ float g_gh[3 * HS];
__device__ float g_gi2[3 * HS];
__device__ float g_gh2[3 * HS];
__device__ float g_energ[SS];
__device__ float g_ctx[HS];
__device__ float g_part[NB][HS];         // per-block context partials (deterministic)
__device__ float g_pm[NB];
__device__ float g_ps[NB];
__device__ volatile unsigned g_bar_gen;  // statically 0
__device__ unsigned g_bar_cnt;
__device__ volatile unsigned g_abar_gen; // attn-only barrier
__device__ unsigned g_abar_cnt;

// ---------------- full grid barrier (all 148 blocks, all threads) -------------
__device__ __forceinline__ void grid_barrier() {
    __syncthreads();
    if (threadIdx.x == 0) {
        __threadfence();
        unsigned gen = g_bar_gen;
        if (atomicAdd(&g_bar_cnt, 1u) == NB - 1) {
            g_bar_cnt = 0;
            __threadfence();
            g_bar_gen = gen + 1;
        } else {
            while (g_bar_gen == gen) __nanosleep(32);
            __threadfence();
        }
    }
    __syncthreads();
}

// ---------------- attn-warps-only grid barrier (128 threads/block) ------------
__device__ __forceinline__ void attn_grid_barrier() {
    asm volatile("bar.sync 1, 128;" ::: "memory");
    if (threadIdx.x == CW * 32) {
        __threadfence();
        unsigned gen = g_abar_gen;
        if (atomicAdd(&g_abar_cnt, 1u) == NB - 1) {
            g_abar_cnt = 0;
            __threadfence();
            g_abar_gen = gen + 1;
        } else {
            while (g_abar_gen == gen) __nanosleep(32);
            __threadfence();
        }
    }
    asm volatile("bar.sync 1, 128;" ::: "memory");
}

// ---------------- reductions --------------------------------------------------
__device__ __forceinline__ float warpSum(float v) {
    #pragma unroll
    for (int o = 16; o > 0; o >>= 1) v += __shfl_down_sync(0xffffffffu, v, o);
    return v;
}
__device__ __forceinline__ float warpMax(float v) {
    #pragma unroll
    for (int o = 16; o > 0; o >>= 1) v = fmaxf(v, __shfl_down_sync(0xffffffffu, v, o));
    return v;
}
__device__ __forceinline__ float blockSum(float v, float* sm) {  // thread 0 valid
    int lane = threadIdx.x & 31, wid = threadIdx.x >> 5;
    v = warpSum(v);
    if (lane == 0) sm[wid] = v;
    __syncthreads();
    float r = (threadIdx.x < NWB) ? sm[threadIdx.x] : 0.0f;
    __syncthreads();
    if (wid == 0) r = warpSum(r);
    return r;
}
__device__ __forceinline__ float blockMax(float v, float* sm) {  // thread 0 valid
    int lane = threadIdx.x & 31, wid = threadIdx.x >> 5;
    v = warpMax(v);
    if (lane == 0) sm[wid] = v;
    __syncthreads();
    float r = (threadIdx.x < NWB) ? sm[threadIdx.x] : -INFINITY;
    __syncthreads();
    if (wid == 0) r = warpMax(r);
    return r;
}

__device__ __forceinline__ float fma4(float4 w, float4 x, float a) {
    return fmaf(w.x, x.x, fmaf(w.y, x.y, fmaf(w.z, x.z, fmaf(w.w, x.w, a))));
}
__device__ __forceinline__ float sigmoidf_(float x) { return 1.0f / (1.0f + expf(-x)); }

// 2048-col dot: W row (global) . x (smem float4[512])
__device__ __forceinline__ float dot2048(const float4* __restrict__ Wr,
                                         const float4* __restrict__ sx, int lane) {
    float a0 = 0.f, a1 = 0.f, a2 = 0.f, a3 = 0.f;
    #pragma unroll
    for (int i = 0; i < 4; i++) {
        int idx = lane + 128 * i;
        float4 w0 = __ldg(Wr + idx),       x0 = sx[idx];
        float4 w1 = __ldg(Wr + idx + 32),  x1 = sx[idx + 32];
        float4 w2 = __ldg(Wr + idx + 64),  x2 = sx[idx + 64];
        float4 w3 = __ldg(Wr + idx + 96),  x3 = sx[idx + 96];
        a0 = fma4(w0, x0, a0); a1 = fma4(w1, x1, a1);
        a2 = fma4(w2, x2, a2); a3 = fma4(w3, x3, a3);
    }
    return warpSum((a0 + a1) + (a2 + a3));
}

// 1024-col dot: W row (global) . x (smem float4[256])
__device__ __forceinline__ float dot1024(const float4* __restrict__ Wr,
                                         const float4* __restrict__ sx, int lane) {
    float a0 = 0.f, a1 = 0.f, a2 = 0.f, a3 = 0.f;
    #pragma unroll
    for (int i = 0; i < 2; i++) {
        int idx = lane + 128 * i;
        float4 w0 = __ldg(Wr + idx),       x0 = sx[idx];
        float4 w1 = __ldg(Wr + idx + 32),  x1 = sx[idx + 32];
        float4 w2 = __ldg(Wr + idx + 64),  x2 = sx[idx + 64];
        float4 w3 = __ldg(Wr + idx + 96),  x3 = sx[idx + 96];
        a0 = fma4(w0, x0, a0); a1 = fma4(w1, x1, a1);
        a2 = fma4(w2, x2, a2); a3 = fma4(w3, x3, a3);
    }
    return warpSum((a0 + a1) + (a2 + a3));
}

// 1024-col dot with x cached in 8 float4 regs (xr[k] = x4[lane + 32k]); W streamed
__device__ __forceinline__ float dot1024reg(const float4* __restrict__ Wr,
                                            const float4 xr[8], int lane) {
    float a0 = 0.f, a1 = 0.f, a2 = 0.f, a3 = 0.f;
    #pragma unroll
    for (int i = 0; i < 2; i++) {
        int idx = lane + 128 * i;
        float4 w0 = __ldcs(Wr + idx);
        float4 w1 = __ldcs(Wr + idx + 32);
        float4 w2 = __ldcs(Wr + idx + 64);
        float4 w3 = __ldcs(Wr + idx + 96);
        a0 = fma4(w0, xr[4 * i + 0], a0);
        a1 = fma4(w1, xr[4 * i + 1], a1);
        a2 = fma4(w2, xr[4 * i + 2], a2);
        a3 = fma4(w3, xr[4 * i + 3], a3);
    }
    return warpSum((a0 + a1) + (a2 + a3));
}

// ---------------- the single fused kernel -------------------------------------
__global__ void __launch_bounds__(NT, 1)
fused_seq2seq(const int* __restrict__ word,
              const float* __restrict__ ctx_in,
              const float* __restrict__ hid_in,     // (2, H)
              const float* __restrict__ enc,        // (S, H)
              const float* __restrict__ emb,
              const float* __restrict__ Wih0, const float* __restrict__ Whh0,
              const float* __restrict__ bih0, const float* __restrict__ bhh0,
              const float* __restrict__ Wih1, const float* __restrict__ Whh1,
              const float* __restrict__ bih1, const float* __restrict__ bhh1,
              const float* __restrict__ Wout, const float* __restrict__ bout,
              float* __restrict__ out_logits, float* __restrict__ out_ctx,
              float* __restrict__ out_hid0, float* __restrict__ out_hid1,
              float* __restrict__ out_attn) {
    __shared__ float4 s_x4[512];            // 8 KB x buffer (2048 floats)
    __shared__ float4 s_h4[256];            // 4 KB secondary x buffer
    __shared__ float  s_red[32];
    __shared__ float  s_bc;
    __shared__ float  s_w[CHS];
    __shared__ float  s_am[ATW], s_as[ATW]; // attn-group reduce buffers

    float* s_x = (float*)s_x4;
    float* s_h = (float*)s_h4;

    const int tid  = threadIdx.x;
    const int lane = tid & 31;
    const int wid  = tid >> 5;
    const int gw   = blockIdx.x * NWB + wid;

    // ── ph1: layer-0 matvecs.  x0=[emb,ctx] in s_x, hid0prev in s_h ──
    s_x[tid]      = emb[(size_t)word[0] * HS + tid];
    s_x[HS + tid] = ctx_in[tid];
    s_h[tid]      = hid_in[tid];
    __syncthreads();
    for (int t = gw; t < 6 * HS; t += NWARPS) {
        if (t < 3 * HS) {
            float a = dot2048((const float4*)(Wih0 + (size_t)t * (2 * HS)), s_x4, lane);
            if (lane == 0) g_gi[t] = a + __ldg(bih0 + t);
        } else {
            int row = t - 3 * HS;
            float a = dot1024((const float4*)(Whh0 + (size_t)row * HS), s_h4, lane);
            if (lane == 0) g_gh[row] = a + __ldg(bhh0 + row);
        }
    }
    grid_barrier();  // B1

    // ── ph2: redundant layer-0 gates -> s_x[0:H); h1prev -> s_h ──
    {
        float r = sigmoidf_(g_gi[tid] + g_gh[tid]);
        float z = sigmoidf_(g_gi[HS + tid] + g_gh[HS + tid]);
        float n = tanhf(g_gi[2 * HS + tid] + r * g_gh[2 * HS + tid]);
        float h = (1.0f - z) * n + z * hid_in[tid];
        if (blockIdx.x == 0) out_hid0[tid] = h;
        float h1prev = hid_in[HS + tid];
        __syncthreads();
        s_x[tid] = h;
        s_h[tid] = h1prev;
    }
    __syncthreads();

    // ── ph3: layer-1 matvecs ──
    for (int t = gw; t < 6 * HS; t += NWARPS) {
        if (t < 3 * HS) {
            float a = dot1024((const float4*)(Wih1 + (size_t)t * HS), s_x4, lane);
            if (lane == 0) g_gi2[t] = a + __ldg(bih1 + t);
        } else {
            int row = t - 3 * HS;
            float a = dot1024((const float4*)(Whh1 + (size_t)row * HS), s_h4, lane);
            if (lane == 0) g_gh2[row] = a + __ldg(bhh1 + row);
        }
    }
    grid_barrier();  // B3

    // ── ph4: redundant layer-1 gates -> h1 in s_x[0:H) ──
    {
        float r = sigmoidf_(g_gi2[tid] + g_gh2[tid]);
        float z = sigmoidf_(g_gi2[HS + tid] + g_gh2[HS + tid]);
        float n = tanhf(g_gi2[2 * HS + tid] + r * g_gh2[2 * HS + tid]);
        float h = (1.0f - z) * n + z * hid_in[HS + tid];
        if (blockIdx.x == 0) out_hid1[tid] = h;
        __syncthreads();
        s_x[tid] = h;
    }
    __syncthreads();   // h1 visible to all warps; NO barrier crossed before convergence

    const int base  = blockIdx.x * CHV;
    const int nrows = min(CHV, VS - base);

    // ═══ WARP SPECIALIZATION: compute warps stream W_out·h1; attn warps do attention ═══
    if (wid < CW) {
        // ---- half-A: logits partial = W_out[row, 0:1024] . h1 + bias ----
        float4 xr[8];
        #pragma unroll
        for (int k = 0; k < 8; k++) xr[k] = s_x4[lane + 32 * k];
        for (int r = wid; r < nrows; r += CW) {
            int row = base + r;
            float a = dot1024reg((const float4*)(Wout + (size_t)row * (2 * HS)), xr, lane);
            if (lane == 0) out_logits[row] = a + __ldg(bout + row);
        }
    } else {
        // ---- attention chain on 4 warps/block (128 threads), overlapped ----
        const int tid2 = tid - CW * 32;        // 0..127
        const int awid = wid - CW;             // 0..3
        const int aw   = blockIdx.x * ATW + awid;

        // energies: warp-per-row over 592 warps
        for (int t = aw; t < SS; t += AWN) {
            float a = dot1024((const float4*)(enc + (size_t)t * HS), s_x4, lane);
            if (lane == 0) g_energ[t] = a;
        }
        attn_grid_barrier();   // A1: all energies ready

        // softmax normalizer (redundant per block, 128 threads, 16 vals each)
        float e[16];
        float ml = -INFINITY;
        #pragma unroll
        for (int j = 0; j < 16; j++) {
            e[j] = g_energ[tid2 + 128 * j];
            ml = fmaxf(ml, e[j]);
        }
        ml = warpMax(ml);
        if (lane == 0) s_am[awid] = ml;
        asm volatile("bar.sync 1, 128;" ::: "memory");
        float mx = fmaxf(fmaxf(s_am[0], s_am[1]), fmaxf(s_am[2], s_am[3]));
        float sl = 0.0f;
        #pragma unroll
        for (int j = 0; j < 16; j++) sl += expf(e[j] - mx);
        sl = warpSum(sl);
        if (lane == 0) s_as[awid] = sl;
        asm volatile("bar.sync 1, 128;" ::: "memory");
        float inv = 1.0f / (s_as[0] + s_as[1] + s_as[2] + s_as[3]);

        // weights for this block's s-slice
        int s0 = blockIdx.x * CHS;
        int ns = min(CHS, SS - s0); if (ns < 0) ns = 0;
        if (tid2 < ns) {
            float wv = expf(g_energ[s0 + tid2] - mx) * inv;
            s_w[tid2] = wv;
            out_attn[s0 + tid2] = wv;
        }
        asm volatile("bar.sync 1, 128;" ::: "memory");

        // context partial: 8 columns per thread over ns s-rows
        {
            int c = tid2 * 8;
            float acc[8] = {0,0,0,0,0,0,0,0};
            for (int j = 0; j < ns; j++) {
                float wv = s_w[j];
                const float4* ep = (const float4*)(enc + (size_t)(s0 + j) * HS + c);
                float4 e0 = __ldg(ep), e1 = __ldg(ep + 1);
                acc[0] = fmaf(wv, e0.x, acc[0]); acc[1] = fmaf(wv, e0.y, acc[1]);
                acc[2] = fmaf(wv, e0.z, acc[2]); acc[3] = fmaf(wv, e0.w, acc[3]);
                acc[4] = fmaf(wv, e1.x, acc[4]); acc[5] = fmaf(wv, e1.y, acc[5]);
                acc[6] = fmaf(wv, e1.z, acc[6]); acc[7] = fmaf(wv, e1.w, acc[7]);
            }
            float* gp = &g_part[blockIdx.x][c];
            #pragma unroll
            for (int k = 0; k < 8; k++) gp[k] = acc[k];
        }
        attn_grid_barrier();   // A2: all partials ready

        // reduce partials: block owns CHH columns
        if (tid2 < CHH) {
            int c = blockIdx.x * CHH + tid2;
            if (c < HS) {
                float s = 0.0f;
                #pragma unroll 4
                for (int b = 0; b < NB; b++) s += g_part[b][c];
                g_ctx[c] = s;
                out_ctx[c] = s;
            }
        }
        attn_grid_barrier();   // A3: g_ctx fully published chip-wide
    }
    __syncthreads();   // convergence: this block's attn warps passed A3 -> ctx ready

    // ── half-B: logits += W_out[row, 1024:2048] . ctx  (all 32 warps) ──
    {
        s_x[tid] = g_ctx[tid];
        __syncthreads();
        float4 xr[8];
        #pragma unroll
        for (int k = 0; k < 8; k++) xr[k] = s_x4[lane + 32 * k];
        for (int r = wid; r < nrows; r += NWB) {
            int row = base + r;
            float a = dot1024reg((const float4*)(Wout + (size_t)row * (2 * HS) + HS), xr, lane);
            if (lane == 0) out_logits[row] += a;
        }
        __syncthreads();

        // ph9a: block-local max/sum-exp over own rows
        bool valid = (tid < nrows);
        float v = valid ? out_logits[base + tid] : -INFINITY;
        float m = blockMax(v, s_red);
        if (tid == 0) s_bc = m;
        __syncthreads();
        float mx = s_bc;
        float s = blockSum(valid ? expf(v - mx) : 0.0f, s_red);
        if (tid == 0) { g_pm[blockIdx.x] = mx; g_ps[blockIdx.x] = s; }
    }
    grid_barrier();  // B9

    // ── ph9b: redundant combine of 148 partials; subtract from own rows ──
    {
        float m = (tid < NB) ? g_pm[tid] : -INFINITY;
        float M = blockMax(m, s_red);
        if (tid == 0) s_bc = M;
        __syncthreads();
        float Mx = s_bc;
        float p = (tid < NB) ? g_ps[tid] * expf(g_pm[tid] - Mx) : 0.0f;
        float S = blockSum(p, s_red);
        if (tid == 0) s_bc = Mx + logf(S);
        __syncthreads();
        float lse = s_bc;
        if (tid < nrows) out_logits[base + tid] -= lse;
    }
}

// ---------------- launch ------------------------------------------------------
extern "C" void kernel_launch(void* const* d_in, const int* in_sizes, int n_in,
                              void* d_out, int out_size) {
    const int*   word         = (const int*)  d_in[0];
    const float* last_context = (const float*)d_in[1];
    const float* last_hidden  = (const float*)d_in[2];
    const float* enc          = (const float*)d_in[3];
    const float* emb          = (const float*)d_in[4];
    const float* W_ih0        = (const float*)d_in[5];
    const float* W_hh0        = (const float*)d_in[6];
    const float* b_ih0        = (const float*)d_in[7];
    const float* b_hh0        = (const float*)d_in[8];
    const float* W_ih1        = (const float*)d_in[9];
    const float* W_hh1        = (const float*)d_in[10];
    const float* b_ih1        = (const float*)d_in[11];
    const float* b_hh1        = (const float*)d_in[12];
    const float* W_out        = (const float*)d_in[13];
    const float* b_out        = (const float*)d_in[14];

    float* out = (float*)d_out;
    float* out_logits = out;                 // V
    float* out_ctx    = out + VS;            // H
    float* out_hid0   = out + VS + HS;       // H
    float* out_hid1   = out + VS + 2 * HS;   // H
    float* out_attn   = out + VS + 3 * HS;   // S

    fused_seq2seq<<<NB, NT>>>(word, last_context, last_hidden, enc, emb,
                              W_ih0, W_hh0, b_ih0, b_hh0,
                              W_ih1, W_hh1, b_ih1, b_hh1,
                              W_out, b_out,
                              out_logits, out_ctx, out_hid0, out_hid1, out_attn);
}

// round 12
// speedup vs baseline: 2.5381x; 1.0007x over previous
#include <cuda_runtime.h>
#include <math.h>

#define HS 1024
#define SS 2048
#define VS 50257
#define NB 148
#define NT 1024
#define NWB 32                      // warps per block
#define NWARPS (NB * NWB)           // 4736
#define CW 28                       // compute (streaming) warps per block
#define ATW 4                       // attention warps per block (tid 896..1023)
#define AWN (NB * ATW)              // 592 attention warps chip-wide
#define CHS ((SS + NB - 1) / NB)    // 14 s-rows per block (context slice)
#define CHV ((VS + NB - 1) / NB)    // 340 logit rows per block
#define CHH ((HS + NB - 1) / NB)    // 7 ctx columns per block (partial reduce)

// ---------------- scratch (device globals; no allocation allowed) -------------
__device__ float g_gi[3 * HS];
__device__ float g_gh[3 * HS];
__device__ float g_gi2[3 * HS];
__device__ float g_gh2[3 * HS];
__device__ float g_energ[SS];
__device__ float g_ctx[HS];
__device__ float g_part[NB][HS];         // per-block context partials (deterministic)
__device__ float g_pm[NB];
__device__ float g_ps[NB];
__device__ volatile unsigned g_bar_gen;  // statically 0
__device__ unsigned g_bar_cnt;
__device__ volatile unsigned g_abar_gen; // attn-only barrier
__device__ unsigned g_abar_cnt;

// ---------------- full grid barrier (all 148 blocks, all threads) -------------
__device__ __forceinline__ void grid_barrier() {
    __syncthreads();
    if (threadIdx.x == 0) {
        __threadfence();
        unsigned gen = g_bar_gen;
        if (atomicAdd(&g_bar_cnt, 1u) == NB - 1) {
            g_bar_cnt = 0;
            __threadfence();
            g_bar_gen = gen + 1;
        } else {
            while (g_bar_gen == gen) __nanosleep(32);
            __threadfence();
        }
    }
    __syncthreads();
}

// ---------------- attn-warps-only grid barrier (128 threads/block) ------------
__device__ __forceinline__ void attn_grid_barrier() {
    asm volatile("bar.sync 1, 128;" ::: "memory");
    if (threadIdx.x == CW * 32) {
        __threadfence();
        unsigned gen = g_abar_gen;
        if (atomicAdd(&g_abar_cnt, 1u) == NB - 1) {
            g_abar_cnt = 0;
            __threadfence();
            g_abar_gen = gen + 1;
        } else {
            while (g_abar_gen == gen) __nanosleep(32);
            __threadfence();
        }
    }
    asm volatile("bar.sync 1, 128;" ::: "memory");
}

// ---------------- reductions --------------------------------------------------
__device__ __forceinline__ float warpSum(float v) {
    #pragma unroll
    for (int o = 16; o > 0; o >>= 1) v += __shfl_down_sync(0xffffffffu, v, o);
    return v;
}
__device__ __forceinline__ float warpMax(float v) {
    #pragma unroll
    for (int o = 16; o > 0; o >>= 1) v = fmaxf(v, __shfl_down_sync(0xffffffffu, v, o));
    return v;
}
__device__ __forceinline__ float blockSum(float v, float* sm) {  // thread 0 valid
    int lane = threadIdx.x & 31, wid = threadIdx.x >> 5;
    v = warpSum(v);
    if (lane == 0) sm[wid] = v;
    __syncthreads();
    float r = (threadIdx.x < NWB) ? sm[threadIdx.x] : 0.0f;
    __syncthreads();
    if (wid == 0) r = warpSum(r);
    return r;
}
__device__ __forceinline__ float blockMax(float v, float* sm) {  // thread 0 valid
    int lane = threadIdx.x & 31, wid = threadIdx.x >> 5;
    v = warpMax(v);
    if (lane == 0) sm[wid] = v;
    __syncthreads();
    float r = (threadIdx.x < NWB) ? sm[threadIdx.x] : -INFINITY;
    __syncthreads();
    if (wid == 0) r = warpMax(r);
    return r;
}

__device__ __forceinline__ float fma4(float4 w, float4 x, float a) {
    return fmaf(w.x, x.x, fmaf(w.y, x.y, fmaf(w.z, x.z, fmaf(w.w, x.w, a))));
}
__device__ __forceinline__ float sigmoidf_(float x) { return 1.0f / (1.0f + expf(-x)); }

// 2048-col dot: streamed W row (__ldcs) . x (smem float4[512])
__device__ __forceinline__ float dot2048s(const float4* __restrict__ Wr,
                                          const float4* __restrict__ sx, int lane) {
    float a0 = 0.f, a1 = 0.f, a2 = 0.f, a3 = 0.f;
    #pragma unroll
    for (int i = 0; i < 4; i++) {
        int idx = lane + 128 * i;
        float4 w0 = __ldcs(Wr + idx),       x0 = sx[idx];
        float4 w1 = __ldcs(Wr + idx + 32),  x1 = sx[idx + 32];
        float4 w2 = __ldcs(Wr + idx + 64),  x2 = sx[idx + 64];
        float4 w3 = __ldcs(Wr + idx + 96),  x3 = sx[idx + 96];
        a0 = fma4(w0, x0, a0); a1 = fma4(w1, x1, a1);
        a2 = fma4(w2, x2, a2); a3 = fma4(w3, x3, a3);
    }
    return warpSum((a0 + a1) + (a2 + a3));
}

// 1024-col dot: cached W/enc row (__ldg) . x (smem float4[256]) — used for enc
__device__ __forceinline__ float dot1024(const float4* __restrict__ Wr,
                                         const float4* __restrict__ sx, int lane) {
    float a0 = 0.f, a1 = 0.f, a2 = 0.f, a3 = 0.f;
    #pragma unroll
    for (int i = 0; i < 2; i++) {
        int idx = lane + 128 * i;
        float4 w0 = __ldg(Wr + idx),       x0 = sx[idx];
        float4 w1 = __ldg(Wr + idx + 32),  x1 = sx[idx + 32];
        float4 w2 = __ldg(Wr + idx + 64),  x2 = sx[idx + 64];
        float4 w3 = __ldg(Wr + idx + 96),  x3 = sx[idx + 96];
        a0 = fma4(w0, x0, a0); a1 = fma4(w1, x1, a1);
        a2 = fma4(w2, x2, a2); a3 = fma4(w3, x3, a3);
    }
    return warpSum((a0 + a1) + (a2 + a3));
}

// 1024-col dot: streamed W row (__ldcs) . x (smem) — GRU weights
__device__ __forceinline__ float dot1024s(const float4* __restrict__ Wr,
                                          const float4* __restrict__ sx, int lane) {
    float a0 = 0.f, a1 = 0.f, a2 = 0.f, a3 = 0.f;
    #pragma unroll
    for (int i = 0; i < 2; i++) {
        int idx = lane + 128 * i;
        float4 w0 = __ldcs(Wr + idx),       x0 = sx[idx];
        float4 w1 = __ldcs(Wr + idx + 32),  x1 = sx[idx + 32];
        float4 w2 = __ldcs(Wr + idx + 64),  x2 = sx[idx + 64];
        float4 w3 = __ldcs(Wr + idx + 96),  x3 = sx[idx + 96];
        a0 = fma4(w0, x0, a0); a1 = fma4(w1, x1, a1);
        a2 = fma4(w2, x2, a2); a3 = fma4(w3, x3, a3);
    }
    return warpSum((a0 + a1) + (a2 + a3));
}

// ---------------- the single fused kernel -------------------------------------
__global__ void __launch_bounds__(NT, 1)
fused_seq2seq(const int* __restrict__ word,
              const float* __restrict__ ctx_in,
              const float* __restrict__ hid_in,     // (2, H)
              const float* __restrict__ enc,        // (S, H)
              const float* __restrict__ emb,
              const float* __restrict__ Wih0, const float* __restrict__ Whh0,
              const float* __restrict__ bih0, const float* __restrict__ bhh0,
              const float* __restrict__ Wih1, const float* __restrict__ Whh1,
              const float* __restrict__ bih1, const float* __restrict__ bhh1,
              const float* __restrict__ Wout, const float* __restrict__ bout,
              float* __restrict__ out_logits, float* __restrict__ out_ctx,
              float* __restrict__ out_hid0, float* __restrict__ out_hid1,
              float* __restrict__ out_attn) {
    __shared__ float4 s_x4[512];            // 8 KB x buffer (2048 floats)
    __shared__ float4 s_h4[256];            // 4 KB secondary x buffer
    __shared__ float  s_red[32];
    __shared__ float  s_bc;
    __shared__ float  s_w[CHS];
    __shared__ float  s_am[ATW], s_as[ATW];

    float* s_x = (float*)s_x4;
    float* s_h = (float*)s_h4;

    const int tid  = threadIdx.x;
    const int lane = tid & 31;
    const int wid  = tid >> 5;
    const int gw   = blockIdx.x * NWB + wid;

    // ── ph1: layer-0 matvecs + HOISTED Whh1·h1prev (all input-only deps) ──
    // s_x = [emb[word], ctx_in] (2048), s_h = h0prev (1024)
    s_x[tid]      = emb[(size_t)word[0] * HS + tid];
    s_x[HS + tid] = ctx_in[tid];
    s_h[tid]      = hid_in[tid];
    __syncthreads();
    for (int t = gw; t < 9 * HS; t += NWARPS) {
        if (t < 3 * HS) {
            float a = dot2048s((const float4*)(Wih0 + (size_t)t * (2 * HS)), s_x4, lane);
            if (lane == 0) g_gi[t] = a + __ldg(bih0 + t);
        } else if (t < 6 * HS) {
            int row = t - 3 * HS;
            float a = dot1024s((const float4*)(Whh0 + (size_t)row * HS), s_h4, lane);
            if (lane == 0) g_gh[row] = a + __ldg(bhh0 + row);
        } else {
            int row = t - 6 * HS;
            // Whh1 . h1prev — h1prev read directly from global (L2-broadcast, 4 KB)
            const float4* h1p = (const float4*)(hid_in + HS);
            float a0 = 0.f, a1 = 0.f, a2 = 0.f, a3 = 0.f;
            const float4* Wr = (const float4*)(Whh1 + (size_t)row * HS);
            #pragma unroll
            for (int i = 0; i < 2; i++) {
                int idx = lane + 128 * i;
                float4 w0 = __ldcs(Wr + idx),       x0 = __ldg(h1p + idx);
                float4 w1 = __ldcs(Wr + idx + 32),  x1 = __ldg(h1p + idx + 32);
                float4 w2 = __ldcs(Wr + idx + 64),  x2 = __ldg(h1p + idx + 64);
                float4 w3 = __ldcs(Wr + idx + 96),  x3 = __ldg(h1p + idx + 96);
                a0 = fma4(w0, x0, a0); a1 = fma4(w1, x1, a1);
                a2 = fma4(w2, x2, a2); a3 = fma4(w3, x3, a3);
            }
            float a = warpSum((a0 + a1) + (a2 + a3));
            if (lane == 0) g_gh2[row] = a + __ldg(bhh1 + row);
        }
    }
    grid_barrier();  // B1

    // ── ph2: redundant layer-0 gates -> h0 in s_x[0:H) ──
    {
        float r = sigmoidf_(g_gi[tid] + g_gh[tid]);
        float z = sigmoidf_(g_gi[HS + tid] + g_gh[HS + tid]);
        float n = tanhf(g_gi[2 * HS + tid] + r * g_gh[2 * HS + tid]);
        float h = (1.0f - z) * n + z * hid_in[tid];
        if (blockIdx.x == 0) out_hid0[tid] = h;
        __syncthreads();
        s_x[tid] = h;
    }
    __syncthreads();

    // ── ph3: layer-1 input matvec only (12.6 MB) ──
    for (int t = gw; t < 3 * HS; t += NWARPS) {
        float a = dot1024s((const float4*)(Wih1 + (size_t)t * HS), s_x4, lane);
        if (lane == 0) g_gi2[t] = a + __ldg(bih1 + t);
    }
    grid_barrier();  // B3

    // ── ph4: redundant layer-1 gates -> h1 in s_x[0:H) ──
    {
        float r = sigmoidf_(g_gi2[tid] + g_gh2[tid]);
        float z = sigmoidf_(g_gi2[HS + tid] + g_gh2[HS + tid]);
        float n = tanhf(g_gi2[2 * HS + tid] + r * g_gh2[2 * HS + tid]);
        float h = (1.0f - z) * n + z * hid_in[HS + tid];
        if (blockIdx.x == 0) out_hid1[tid] = h;
        __syncthreads();
        s_x[tid] = h;
    }
    __syncthreads();   // h1 visible; no grid barrier before convergence

    const int base  = blockIdx.x * CHV;
    const int nrows = min(CHV, VS - base);

    // ═══ WARP SPECIALIZATION: 28 warps stream W_out·h1; 4 warps do attention ═══
    if (wid < CW) {
        // ---- half-A: logits = W_out[row, 0:1024] . h1 + bias ----
        float4 xr[8];
        #pragma unroll
        for (int k = 0; k < 8; k++) xr[k] = s_x4[lane + 32 * k];
        int r = wid;
        for (; r + CW < nrows; r += 2 * CW) {
            int rowA = base + r, rowB = base + r + CW;
            const float4* WA = (const float4*)(Wout + (size_t)rowA * (2 * HS));
            const float4* WB = (const float4*)(Wout + (size_t)rowB * (2 * HS));
            float aA = 0.f, aB = 0.f;
            #pragma unroll
            for (int k = 0; k < 8; k++) {
                float4 wA = __ldcs(WA + lane + 32 * k);
                float4 wB = __ldcs(WB + lane + 32 * k);
                aA = fma4(wA, xr[k], aA);
                aB = fma4(wB, xr[k], aB);
            }
            aA = warpSum(aA);
            aB = warpSum(aB);
            if (lane == 0) {
                out_logits[rowA] = aA + __ldg(bout + rowA);
                out_logits[rowB] = aB + __ldg(bout + rowB);
            }
        }
        if (r < nrows) {
            int row = base + r;
            const float4* WA = (const float4*)(Wout + (size_t)row * (2 * HS));
            float a = 0.f;
            #pragma unroll
            for (int k = 0; k < 8; k++) a = fma4(__ldcs(WA + lane + 32 * k), xr[k], a);
            a = warpSum(a);
            if (lane == 0) out_logits[row] = a + __ldg(bout + row);
        }
    } else {
        // ---- attention chain on 4 warps/block (128 threads), overlapped ----
        const int tid2 = tid - CW * 32;        // 0..127
        const int awid = wid - CW;             // 0..3
        const int aw   = blockIdx.x * ATW + awid;

        for (int t = aw; t < SS; t += AWN) {
            float a = dot1024((const float4*)(enc + (size_t)t * HS), s_x4, lane);
            if (lane == 0) g_energ[t] = a;
        }
        attn_grid_barrier();   // A1: all energies ready

        float e[16];
        float ml = -INFINITY;
        #pragma unroll
        for (int j = 0; j < 16; j++) {
            e[j] = g_energ[tid2 + 128 * j];
            ml = fmaxf(ml, e[j]);
        }
        ml = warpMax(ml);
        if (lane == 0) s_am[awid] = ml;
        asm volatile("bar.sync 1, 128;" ::: "memory");
        float mx = fmaxf(fmaxf(s_am[0], s_am[1]), fmaxf(s_am[2], s_am[3]));
        float sl = 0.0f;
        #pragma unroll
        for (int j = 0; j < 16; j++) sl += expf(e[j] - mx);
        sl = warpSum(sl);
        if (lane == 0) s_as[awid] = sl;
        asm volatile("bar.sync 1, 128;" ::: "memory");
        float inv = 1.0f / (s_as[0] + s_as[1] + s_as[2] + s_as[3]);

        int s0 = blockIdx.x * CHS;
        int ns = min(CHS, SS - s0); if (ns < 0) ns = 0;
        if (tid2 < ns) {
            float wv = expf(g_energ[s0 + tid2] - mx) * inv;
            s_w[tid2] = wv;
            out_attn[s0 + tid2] = wv;
        }
        asm volatile("bar.sync 1, 128;" ::: "memory");

        {
            int c = tid2 * 8;
            float acc[8] = {0,0,0,0,0,0,0,0};
            for (int j = 0; j < ns; j++) {
                float wv = s_w[j];
                const float4* ep = (const float4*)(enc + (size_t)(s0 + j) * HS + c);
                float4 e0 = __ldg(ep), e1 = __ldg(ep + 1);
                acc[0] = fmaf(wv, e0.x, acc[0]); acc[1] = fmaf(wv, e0.y, acc[1]);
                acc[2] = fmaf(wv, e0.z, acc[2]); acc[3] = fmaf(wv, e0.w, acc[3]);
                acc[4] = fmaf(wv, e1.x, acc[4]); acc[5] = fmaf(wv, e1.y, acc[5]);
                acc[6] = fmaf(wv, e1.z, acc[6]); acc[7] = fmaf(wv, e1.w, acc[7]);
            }
            float* gp = &g_part[blockIdx.x][c];
            #pragma unroll
            for (int k = 0; k < 8; k++) gp[k] = acc[k];
        }
        attn_grid_barrier();   // A2: all partials ready

        if (tid2 < CHH) {
            int c = blockIdx.x * CHH + tid2;
            if (c < HS) {
                float s = 0.0f;
                #pragma unroll 4
                for (int b = 0; b < NB; b++) s += g_part[b][c];
                g_ctx[c] = s;
                out_ctx[c] = s;
            }
        }
        attn_grid_barrier();   // A3: g_ctx fully published chip-wide
    }
    __syncthreads();   // convergence: ctx ready (this block's attn warps passed A3)

    // ── half-B: logits += W_out[row, 1024:2048] . ctx  (all 32 warps) ──
    {
        s_x[tid] = g_ctx[tid];
        __syncthreads();
        float4 xr[8];
        #pragma unroll
        for (int k = 0; k < 8; k++) xr[k] = s_x4[lane + 32 * k];
        int r = wid;
        for (; r + NWB < nrows; r += 2 * NWB) {
            int rowA = base + r, rowB = base + r + NWB;
            const float4* WA = (const float4*)(Wout + (size_t)rowA * (2 * HS) + HS);
            const float4* WB = (const float4*)(Wout + (size_t)rowB * (2 * HS) + HS);
            float aA = 0.f, aB = 0.f;
            #pragma unroll
            for (int k = 0; k < 8; k++) {
                float4 wA = __ldcs(WA + lane + 32 * k);
                float4 wB = __ldcs(WB + lane + 32 * k);
                aA = fma4(wA, xr[k], aA);
                aB = fma4(wB, xr[k], aB);
            }
            aA = warpSum(aA);
            aB = warpSum(aB);
            if (lane == 0) {
                out_logits[rowA] += aA;
                out_logits[rowB] += aB;
            }
        }
        if (r < nrows) {
            int row = base + r;
            const float4* WA = (const float4*)(Wout + (size_t)row * (2 * HS) + HS);
            float a = 0.f;
            #pragma unroll
            for (int k = 0; k < 8; k++) a = fma4(__ldcs(WA + lane + 32 * k), xr[k], a);
            a = warpSum(a);
            if (lane == 0) out_logits[row] += a;
        }
        __syncthreads();

        // ph9a: block-local max/sum-exp over own rows
        bool valid = (tid < nrows);
        float v = valid ? out_logits[base + tid] : -INFINITY;
        float m = blockMax(v, s_red);
        if (tid == 0) s_bc = m;
        __syncthreads();
        float mx = s_bc;
        float s = blockSum(valid ? expf(v - mx) : 0.0f, s_red);
        if (tid == 0) { g_pm[blockIdx.x] = mx; g_ps[blockIdx.x] = s; }
    }
    grid_barrier();  // B9

    // ── ph9b: redundant combine of 148 partials; subtract from own rows ──
    {
        float m = (tid < NB) ? g_pm[tid] : -INFINITY;
        float M = blockMax(m, s_red);
        if (tid == 0) s_bc = M;
        __syncthreads();
        float Mx = s_bc;
        float p = (tid < NB) ? g_ps[tid] * expf(g_pm[tid] - Mx) : 0.0f;
        float S = blockSum(p, s_red);
        if (tid == 0) s_bc = Mx + logf(S);
        __syncthreads();
        float lse = s_bc;
        if (tid < nrows) out_logits[base + tid] -= lse;
    }
}

// ---------------- launch ------------------------------------------------------
extern "C" void kernel_launch(void* const* d_in, const int* in_sizes, int n_in,
                              void* d_out, int out_size) {
    const int*   word         = (const int*)  d_in[0];
    const float* last_context = (const float*)d_in[1];
    const float* last_hidden  = (const float*)d_in[2];
    const float* enc          = (const float*)d_in[3];
    const float* emb          = (const float*)d_in[4];
    const float* W_ih0        = (const float*)d_in[5];
    const float* W_hh0        = (const float*)d_in[6];
    const float* b_ih0        = (const float*)d_in[7];
    const float* b_hh0        = (const float*)d_in[8];
    const float* W_ih1        = (const float*)d_in[9];
    const float* W_hh1        = (const float*)d_in[10];
    const float* b_ih1        = (const float*)d_in[11];
    const float* b_hh1        = (const float*)d_in[12];
    const float* W_out        = (const float*)d_in[13];
    const float* b_out        = (const float*)d_in[14];

    float* out = (float*)d_out;
    float* out_logits = out;                 // V
    float* out_ctx    = out + VS;            // H
    float* out_hid0   = out + VS + HS;       // H
    float* out_hid1   = out + VS + 2 * HS;   // H
    float* out_attn   = out + VS + 3 * HS;   // S

    fused_seq2seq<<<NB, NT>>>(word, last_context, last_hidden, enc, emb,
                              W_ih0, W_hh0, b_ih0, b_hh0,
                              W_ih1, W_hh1, b_ih1, b_hh1,
                              W_out, b_out,
                              out_logits, out_ctx, out_hid0, out_hid1, out_attn);
}